// round 4
// baseline (speedup 1.0000x reference)
#include <cuda_runtime.h>
#include <cuda_bf16.h>
#include <cstdint>

#define ND 4096
#define NTE (ND * (size_t)ND)

// ---------------- scratch (device globals; no allocation allowed) ----------
__device__ __align__(1024) __nv_bfloat16 g_Ah[NTE];   // tril(A) hi, [M,K] K-major
__device__ __align__(1024) __nv_bfloat16 g_Al[NTE];   // tril(A) lo
__device__ __align__(1024) __nv_bfloat16 g_Bth[NTE];  // tril(B)^T hi, [N,K] K-major
__device__ __align__(1024) __nv_bfloat16 g_Btl[NTE];  // tril(B)^T lo

// ---------------- helpers ---------------------------------------------------
static __device__ __forceinline__ uint32_t smem_u32(const void* p) {
    return (uint32_t)__cvta_generic_to_shared(p);
}

static __device__ __forceinline__ void cp_async16(uint32_t dst, const void* src) {
    asm volatile("cp.async.cg.shared.global [%0], [%1], 16;" :: "r"(dst), "l"(src));
}
static __device__ __forceinline__ void cp_commit() {
    asm volatile("cp.async.commit_group;" ::: "memory");
}
static __device__ __forceinline__ void cp_wait2() {
    asm volatile("cp.async.wait_group 2;" ::: "memory");
}

static __device__ __forceinline__ void ldsm4(uint32_t& r0, uint32_t& r1,
                                             uint32_t& r2, uint32_t& r3, uint32_t a) {
    asm volatile("ldmatrix.sync.aligned.m8n8.x4.shared.b16 {%0,%1,%2,%3}, [%4];"
                 : "=r"(r0), "=r"(r1), "=r"(r2), "=r"(r3) : "r"(a));
}

static __device__ __forceinline__ void mma16816(float* d, const uint32_t* a,
                                                const uint32_t* b) {
    asm volatile(
        "mma.sync.aligned.m16n8k16.row.col.f32.bf16.bf16.f32 "
        "{%0,%1,%2,%3}, {%4,%5,%6,%7}, {%8,%9}, {%0,%1,%2,%3};"
        : "+f"(d[0]), "+f"(d[1]), "+f"(d[2]), "+f"(d[3])
        : "r"(a[0]), "r"(a[1]), "r"(a[2]), "r"(a[3]), "r"(b[0]), "r"(b[1]));
}

// swizzled smem byte offset inside one 8KB tile: row r (0..127), 16B chunk c (0..3)
static __device__ __forceinline__ uint32_t swz(int r, int c) {
    return (uint32_t)(r * 64 + ((c ^ ((r >> 1) & 3)) << 4));
}

// ---------------- pre-pass: mask + bf16 hi/lo split of A --------------------
__global__ void convert_split_A(const float* __restrict__ A) {
    size_t idx  = (size_t)blockIdx.x * blockDim.x + threadIdx.x;   // one float4
    size_t base = idx * 4;
    int i = (int)(base >> 12);     // row
    int k = (int)(base & 4095);    // col
    float4 v = *(const float4*)(A + base);
    float vv[4] = {v.x, v.y, v.z, v.w};
    __nv_bfloat16 h[4], l[4];
#pragma unroll
    for (int e = 0; e < 4; ++e) {
        float x = ((k + e) <= i) ? vv[e] : 0.0f;
        __nv_bfloat16 hi = __float2bfloat16(x);
        float res = x - __bfloat162float(hi);
        h[e] = hi;
        l[e] = __float2bfloat16(res);
    }
    __nv_bfloat162* ah = (__nv_bfloat162*)(g_Ah + base);
    __nv_bfloat162* al = (__nv_bfloat162*)(g_Al + base);
    ah[0] = __nv_bfloat162(h[0], h[1]); ah[1] = __nv_bfloat162(h[2], h[3]);
    al[0] = __nv_bfloat162(l[0], l[1]); al[1] = __nv_bfloat162(l[2], l[3]);
}

// ---------------- pre-pass: mask + transpose + split of B -------------------
__global__ void transpose_split_B(const float* __restrict__ B) {
    __shared__ float tile[32][33];
    const int bk = blockIdx.y;   // k-tile
    const int bn = blockIdx.x;   // n-tile
    const int tx = threadIdx.x;  // 0..31
    const int ty = threadIdx.y;  // 0..7
    const int k0 = bk * 32, n0 = bn * 32;
#pragma unroll
    for (int r = ty; r < 32; r += 8) {
        int k = k0 + r, n = n0 + tx;
        float v = B[(size_t)k * ND + n];
        tile[r][tx] = (n <= k) ? v : 0.0f;
    }
    __syncthreads();
#pragma unroll
    for (int r = ty; r < 32; r += 8) {
        int n = n0 + r, k = k0 + tx;
        float x = tile[tx][r];   // = masked B[k][n]
        __nv_bfloat16 hi = __float2bfloat16(x);
        float res = x - __bfloat162float(hi);
        g_Bth[(size_t)n * ND + k] = hi;
        g_Btl[(size_t)n * ND + k] = __float2bfloat16(res);
    }
}

// ---------------- zero the output ------------------------------------------
__global__ void zero_out(float4* __restrict__ C) {
    size_t i = (size_t)blockIdx.x * blockDim.x + threadIdx.x;
    C[i] = make_float4(0.f, 0.f, 0.f, 0.f);
}

// ---------------- main GEMM: mma.sync bf16 x3, lower tiles only -------------
#define STAGES 4
#define TILE_BYTES 8192                     // one 128x32 bf16 tile
#define STAGE_BYTES (4 * TILE_BYTES)        // Ah, Al, Bh, Bl
#define GEMM_SMEM (STAGES * STAGE_BYTES)    // 131072

__global__ __launch_bounds__(256, 1)
void trimm_gemm(float* __restrict__ C) {
    extern __shared__ char smem[];
    const uint32_t sb = smem_u32(smem);
    const int tid = threadIdx.x;
    const int wid = tid >> 5;
    const int lid = tid & 31;
    const int wm = wid & 1;        // 0..1 (M)
    const int wn = wid >> 1;       // 0..3 (N)

    // tile map: heaviest diagonals first (d = bi-bj descending)
    int id = blockIdx.x;
    int dd, cum = 0;
    for (dd = 31; dd > 0; --dd) {
        int cnt = 32 - dd;
        if (id < cum + cnt) break;
        cum += cnt;
    }
    const int bj = id - cum;
    const int bi = bj + dd;

    const int kt0 = bj * 128;
    const int KT  = (bi - bj + 1) * 4;   // number of K=32 stages (>= 4)

    // per-thread cp.async chunk coords: two chunks per 8KB tile
    const int r0g = tid >> 2, c0g = tid & 3;               // chunk tid
    const int r1g = (tid + 256) >> 2, c1g = tid & 3;       // chunk tid+256

    const __nv_bfloat16* srcs[4] = {g_Ah, g_Al, g_Bth, g_Btl};
    const int rowbase[4] = {bi * 128, bi * 128, bj * 128, bj * 128};

    // issue one stage's loads
    auto issue = [&](int s, int kt) {
        uint32_t stage_base = sb + (uint32_t)s * STAGE_BYTES;
#pragma unroll
        for (int a = 0; a < 4; ++a) {
            const __nv_bfloat16* src = srcs[a];
            uint32_t tb = stage_base + a * TILE_BYTES;
            cp_async16(tb + swz(r0g, c0g),
                       src + (size_t)(rowbase[a] + r0g) * ND + kt + c0g * 8);
            cp_async16(tb + swz(r1g, c1g),
                       src + (size_t)(rowbase[a] + r1g) * ND + kt + c1g * 8);
        }
    };

    float acc[4][4][4];
#pragma unroll
    for (int a = 0; a < 4; ++a)
#pragma unroll
        for (int b = 0; b < 4; ++b)
#pragma unroll
            for (int c = 0; c < 4; ++c) acc[a][b][c] = 0.f;

    // prologue: stages 0,1 (KT >= 4 always)
    issue(0, kt0);      cp_commit();
    issue(1, kt0 + 32); cp_commit();

    const int g  = lid >> 3;   // ldmatrix group 0..3
    const int rr = lid & 7;

    for (int i = 0; i < KT; ++i) {
        int is = i + 2;
        if (is < KT) issue(is & 3, kt0 + is * 32);
        cp_commit();           // commit EVERY iteration (possibly empty group)
        cp_wait2();            // commits == i+3  ->  stages <= i complete
        __syncthreads();

        const uint32_t stage = sb + (uint32_t)(i & 3) * STAGE_BYTES;
        const uint32_t aH = stage;
        const uint32_t bH = stage + 2 * TILE_BYTES;

#pragma unroll
        for (int ks = 0; ks < 2; ++ks) {
            const int c0 = ks * 2;
            uint32_t ah[4][4], al[4][4], bh[4][2], bl[4][2];

            // A fragments: 4 m-tiles, hi & lo
#pragma unroll
            for (int tm = 0; tm < 4; ++tm) {
                int r = wm * 64 + tm * 16 + (g & 1) * 8 + rr;
                uint32_t off = swz(r, c0 + (g >> 1));
                ldsm4(ah[tm][0], ah[tm][1], ah[tm][2], ah[tm][3], aH + off);
                ldsm4(al[tm][0], al[tm][1], al[tm][2], al[tm][3], aH + TILE_BYTES + off);
            }
            // B fragments: 4 n-tiles (two x4 loads cover 16 n each), hi & lo
#pragma unroll
            for (int p = 0; p < 2; ++p) {
                int r = wn * 32 + p * 16 + (g >> 1) * 8 + rr;
                uint32_t off = swz(r, c0 + (g & 1));
                uint32_t h0, h1, h2, h3;
                ldsm4(h0, h1, h2, h3, bH + off);
                bh[p * 2 + 0][0] = h0; bh[p * 2 + 0][1] = h1;
                bh[p * 2 + 1][0] = h2; bh[p * 2 + 1][1] = h3;
                ldsm4(h0, h1, h2, h3, bH + TILE_BYTES + off);
                bl[p * 2 + 0][0] = h0; bl[p * 2 + 0][1] = h1;
                bl[p * 2 + 1][0] = h2; bl[p * 2 + 1][1] = h3;
            }
            // 48 MMAs
#pragma unroll
            for (int tm = 0; tm < 4; ++tm)
#pragma unroll
                for (int tn = 0; tn < 4; ++tn) {
                    mma16816(acc[tm][tn], ah[tm], bh[tn]);
                    mma16816(acc[tm][tn], ah[tm], bl[tn]);
                    mma16816(acc[tm][tn], al[tm], bh[tn]);
                }
        }
        __syncthreads();
    }

    // epilogue: write fp32 accumulators to C
#pragma unroll
    for (int tm = 0; tm < 4; ++tm) {
#pragma unroll
        for (int tn = 0; tn < 4; ++tn) {
            int row = bi * 128 + wm * 64 + tm * 16 + (lid >> 2);
            int col = bj * 128 + wn * 32 + tn * 8 + (lid & 3) * 2;
            float2 v0 = make_float2(acc[tm][tn][0], acc[tm][tn][1]);
            float2 v1 = make_float2(acc[tm][tn][2], acc[tm][tn][3]);
            *(float2*)(C + (size_t)row * ND + col)       = v0;
            *(float2*)(C + (size_t)(row + 8) * ND + col) = v1;
        }
    }
}

// ---------------- launch ----------------------------------------------------
extern "C" void kernel_launch(void* const* d_in, const int* in_sizes, int n_in,
                              void* d_out, int out_size) {
    const float* A = (const float*)d_in[0];
    const float* B = (const float*)d_in[1];
    float* C = (float*)d_out;

    cudaFuncSetAttribute(trimm_gemm, cudaFuncAttributeMaxDynamicSharedMemorySize, GEMM_SMEM);

    convert_split_A<<<16384, 256>>>(A);
    transpose_split_B<<<dim3(128, 128), dim3(32, 8)>>>(B);
    zero_out<<<16384, 256>>>((float4*)C);
    trimm_gemm<<<528, 256, GEMM_SMEM>>>(C);
}

// round 5
// speedup vs baseline: 1.2530x; 1.2530x over previous
#include <cuda_runtime.h>
#include <cuda_bf16.h>
#include <cstdint>

#define ND 4096
#define NTE (ND * (size_t)ND)

// ---------------- scratch (device globals; no allocation allowed) ----------
__device__ __align__(1024) __nv_bfloat16 g_Ah[NTE];   // tril(A) hi, [M,K] K-major
__device__ __align__(1024) __nv_bfloat16 g_Al[NTE];   // tril(A) lo
__device__ __align__(1024) __nv_bfloat16 g_Bth[NTE];  // tril(B)^T hi, [N,K] K-major
__device__ __align__(1024) __nv_bfloat16 g_Btl[NTE];  // tril(B)^T lo

// ---------------- helpers ---------------------------------------------------
static __device__ __forceinline__ uint32_t smem_u32(const void* p) {
    return (uint32_t)__cvta_generic_to_shared(p);
}

static __device__ __forceinline__ void cp_async16(uint32_t dst, const void* src) {
    asm volatile("cp.async.cg.shared.global [%0], [%1], 16;" :: "r"(dst), "l"(src));
}
static __device__ __forceinline__ void cp_commit() {
    asm volatile("cp.async.commit_group;" ::: "memory");
}
static __device__ __forceinline__ void cp_wait2() {
    asm volatile("cp.async.wait_group 2;" ::: "memory");
}

static __device__ __forceinline__ void ldsm4(uint32_t& r0, uint32_t& r1,
                                             uint32_t& r2, uint32_t& r3, uint32_t a) {
    asm volatile("ldmatrix.sync.aligned.m8n8.x4.shared.b16 {%0,%1,%2,%3}, [%4];"
                 : "=r"(r0), "=r"(r1), "=r"(r2), "=r"(r3) : "r"(a));
}

static __device__ __forceinline__ void mma16816(float* d, const uint32_t* a,
                                                const uint32_t* b) {
    asm volatile(
        "mma.sync.aligned.m16n8k16.row.col.f32.bf16.bf16.f32 "
        "{%0,%1,%2,%3}, {%4,%5,%6,%7}, {%8,%9}, {%0,%1,%2,%3};"
        : "+f"(d[0]), "+f"(d[1]), "+f"(d[2]), "+f"(d[3])
        : "r"(a[0]), "r"(a[1]), "r"(a[2]), "r"(a[3]), "r"(b[0]), "r"(b[1]));
}

// swizzled smem byte offset inside one 8KB tile: row r (0..127), 16B chunk c (0..3)
static __device__ __forceinline__ uint32_t swz(int r, int c) {
    return (uint32_t)(r * 64 + ((c ^ ((r >> 1) & 3)) << 4));
}

// ---------------- pre-pass: mask + bf16 hi/lo split of A (lower blocks only) -
__global__ void convert_split_A(const float* __restrict__ A) {
    size_t idx  = (size_t)blockIdx.x * blockDim.x + threadIdx.x;   // one float4
    size_t base = idx * 4;
    int i = (int)(base >> 12);     // row
    int k = (int)(base & 4095);    // col
    // cull strictly-upper 128x128 blocks: never read by the GEMM (warp-uniform)
    if ((k >> 7) > (i >> 7)) return;
    float4 v = *(const float4*)(A + base);
    float vv[4] = {v.x, v.y, v.z, v.w};
    __nv_bfloat16 h[4], l[4];
#pragma unroll
    for (int e = 0; e < 4; ++e) {
        float x = ((k + e) <= i) ? vv[e] : 0.0f;
        __nv_bfloat16 hi = __float2bfloat16(x);
        float res = x - __bfloat162float(hi);
        h[e] = hi;
        l[e] = __float2bfloat16(res);
    }
    __nv_bfloat162* ah = (__nv_bfloat162*)(g_Ah + base);
    __nv_bfloat162* al = (__nv_bfloat162*)(g_Al + base);
    ah[0] = __nv_bfloat162(h[0], h[1]); ah[1] = __nv_bfloat162(h[2], h[3]);
    al[0] = __nv_bfloat162(l[0], l[1]); al[1] = __nv_bfloat162(l[2], l[3]);
}

// ---------------- pre-pass: mask + transpose + split of B (lower of B^T only)
__global__ void transpose_split_B(const float* __restrict__ B) {
    __shared__ float tile[32][33];
    const int bk = blockIdx.y;   // k-tile
    const int bn = blockIdx.x;   // n-tile
    // output rows n in bn-tile, cols k in bk-tile; GEMM reads only k-block >= n-block
    if (bn > bk) return;
    const int tx = threadIdx.x;  // 0..31
    const int ty = threadIdx.y;  // 0..7
    const int k0 = bk * 32, n0 = bn * 32;
#pragma unroll
    for (int r = ty; r < 32; r += 8) {
        int k = k0 + r, n = n0 + tx;
        float v = B[(size_t)k * ND + n];
        tile[r][tx] = (n <= k) ? v : 0.0f;
    }
    __syncthreads();
#pragma unroll
    for (int r = ty; r < 32; r += 8) {
        int n = n0 + r, k = k0 + tx;
        float x = tile[tx][r];   // = masked B[k][n]
        __nv_bfloat16 hi = __float2bfloat16(x);
        float res = x - __bfloat162float(hi);
        g_Bth[(size_t)n * ND + k] = hi;
        g_Btl[(size_t)n * ND + k] = __float2bfloat16(res);
    }
}

// ---------------- main GEMM: mma.sync bf16 x3 + upper-tile zeroing ----------
#define STAGES 4
#define TILE_BYTES 8192                     // one 128x32 bf16 tile
#define STAGE_BYTES (4 * TILE_BYTES)        // Ah, Al, Bh, Bl
#define GEMM_SMEM (STAGES * STAGE_BYTES)    // 131072

__global__ __launch_bounds__(256, 1)
void trimm_gemm(float* __restrict__ C) {
    extern __shared__ char smem[];
    const uint32_t sb = smem_u32(smem);
    const int tid = threadIdx.x;

    // ---- blocks >= 528: zero one strictly-upper 128x128 tile and exit ------
    if (blockIdx.x >= 528) {
        int uid = blockIdx.x - 528;
        int r, cum = 0;
        for (r = 0; r < 32; ++r) {
            int cnt = 31 - r;
            if (uid < cum + cnt) break;
            cum += cnt;
        }
        const int zbi = r, zbj = r + 1 + (uid - cum);
        float4* dst = (float4*)(C + (size_t)zbi * 128 * ND + zbj * 128);
        const float4 z = make_float4(0.f, 0.f, 0.f, 0.f);
#pragma unroll
        for (int it = 0; it < 16; ++it) {
            int c = it * 256 + tid;          // 0..4095 float4 chunks
            int row = c >> 5, q = c & 31;
            dst[(size_t)row * (ND / 4) + q] = z;
        }
        return;
    }

    const int wid = tid >> 5;
    const int lid = tid & 31;
    const int wm = wid & 1;        // 0..1 (M)
    const int wn = wid >> 1;       // 0..3 (N)

    // tile map: heaviest diagonals first (d = bi-bj descending)
    int id = blockIdx.x;
    int dd, cum = 0;
    for (dd = 31; dd > 0; --dd) {
        int cnt = 32 - dd;
        if (id < cum + cnt) break;
        cum += cnt;
    }
    const int bj = id - cum;
    const int bi = bj + dd;

    const int kt0 = bj * 128;
    const int KT  = (bi - bj + 1) * 4;   // number of K=32 stages (>= 4)

    // per-thread cp.async chunk coords: two chunks per 8KB tile
    const int r0g = tid >> 2, c0g = tid & 3;               // chunk tid
    const int r1g = (tid + 256) >> 2, c1g = tid & 3;       // chunk tid+256

    const __nv_bfloat16* srcs[4] = {g_Ah, g_Al, g_Bth, g_Btl};
    const int rowbase[4] = {bi * 128, bi * 128, bj * 128, bj * 128};

    // issue one stage's loads
    auto issue = [&](int s, int kt) {
        uint32_t stage_base = sb + (uint32_t)s * STAGE_BYTES;
#pragma unroll
        for (int a = 0; a < 4; ++a) {
            const __nv_bfloat16* src = srcs[a];
            uint32_t tb = stage_base + a * TILE_BYTES;
            cp_async16(tb + swz(r0g, c0g),
                       src + (size_t)(rowbase[a] + r0g) * ND + kt + c0g * 8);
            cp_async16(tb + swz(r1g, c1g),
                       src + (size_t)(rowbase[a] + r1g) * ND + kt + c1g * 8);
        }
    };

    float acc[4][4][4];
#pragma unroll
    for (int a = 0; a < 4; ++a)
#pragma unroll
        for (int b = 0; b < 4; ++b)
#pragma unroll
            for (int c = 0; c < 4; ++c) acc[a][b][c] = 0.f;

    // prologue: stages 0,1 (KT >= 4 always)
    issue(0, kt0);      cp_commit();
    issue(1, kt0 + 32); cp_commit();

    const int g  = lid >> 3;   // ldmatrix group 0..3
    const int rr = lid & 7;

    for (int i = 0; i < KT; ++i) {
        int is = i + 2;
        if (is < KT) issue(is & 3, kt0 + is * 32);
        cp_commit();           // commit EVERY iteration (possibly empty group)
        cp_wait2();            // commits == i+3  ->  stages <= i complete
        __syncthreads();       // single barrier per stage (safe: STAGES=4, skew<1 iter)

        const uint32_t stage = sb + (uint32_t)(i & 3) * STAGE_BYTES;
        const uint32_t aH = stage;
        const uint32_t bH = stage + 2 * TILE_BYTES;

#pragma unroll
        for (int ks = 0; ks < 2; ++ks) {
            const int c0 = ks * 2;
            uint32_t ah[4][4], al[4][4], bh[4][2], bl[4][2];

            // A fragments: 4 m-tiles, hi & lo
#pragma unroll
            for (int tm = 0; tm < 4; ++tm) {
                int r = wm * 64 + tm * 16 + (g & 1) * 8 + rr;
                uint32_t off = swz(r, c0 + (g >> 1));
                ldsm4(ah[tm][0], ah[tm][1], ah[tm][2], ah[tm][3], aH + off);
                ldsm4(al[tm][0], al[tm][1], al[tm][2], al[tm][3], aH + TILE_BYTES + off);
            }
            // B fragments: 4 n-tiles (two x4 loads cover 16 n each), hi & lo
#pragma unroll
            for (int p = 0; p < 2; ++p) {
                int r = wn * 32 + p * 16 + (g >> 1) * 8 + rr;
                uint32_t off = swz(r, c0 + (g & 1));
                uint32_t h0, h1, h2, h3;
                ldsm4(h0, h1, h2, h3, bH + off);
                bh[p * 2 + 0][0] = h0; bh[p * 2 + 0][1] = h1;
                bh[p * 2 + 1][0] = h2; bh[p * 2 + 1][1] = h3;
                ldsm4(h0, h1, h2, h3, bH + TILE_BYTES + off);
                bl[p * 2 + 0][0] = h0; bl[p * 2 + 0][1] = h1;
                bl[p * 2 + 1][0] = h2; bl[p * 2 + 1][1] = h3;
            }
            // 48 MMAs
#pragma unroll
            for (int tm = 0; tm < 4; ++tm)
#pragma unroll
                for (int tn = 0; tn < 4; ++tn) {
                    mma16816(acc[tm][tn], ah[tm], bh[tn]);
                    mma16816(acc[tm][tn], ah[tm], bl[tn]);
                    mma16816(acc[tm][tn], al[tm], bh[tn]);
                }
        }
    }

    // epilogue: write fp32 accumulators to C
#pragma unroll
    for (int tm = 0; tm < 4; ++tm) {
#pragma unroll
        for (int tn = 0; tn < 4; ++tn) {
            int row = bi * 128 + wm * 64 + tm * 16 + (lid >> 2);
            int col = bj * 128 + wn * 32 + tn * 8 + (lid & 3) * 2;
            float2 v0 = make_float2(acc[tm][tn][0], acc[tm][tn][1]);
            float2 v1 = make_float2(acc[tm][tn][2], acc[tm][tn][3]);
            *(float2*)(C + (size_t)row * ND + col)       = v0;
            *(float2*)(C + (size_t)(row + 8) * ND + col) = v1;
        }
    }
}

// ---------------- launch ----------------------------------------------------
extern "C" void kernel_launch(void* const* d_in, const int* in_sizes, int n_in,
                              void* d_out, int out_size) {
    const float* A = (const float*)d_in[0];
    const float* B = (const float*)d_in[1];
    float* C = (float*)d_out;

    cudaFuncSetAttribute(trimm_gemm, cudaFuncAttributeMaxDynamicSharedMemorySize, GEMM_SMEM);

    convert_split_A<<<16384, 256>>>(A);
    transpose_split_B<<<dim3(128, 128), dim3(32, 8)>>>(B);
    trimm_gemm<<<1024, 256, GEMM_SMEM>>>(C);
}

// round 7
// speedup vs baseline: 1.2701x; 1.0137x over previous
#include <cuda_runtime.h>
#include <cuda_bf16.h>
#include <cstdint>

#define ND 4096
#define NTE (ND * (size_t)ND)

// ---------------- scratch (device globals; no allocation allowed) ----------
__device__ __align__(1024) __nv_bfloat16 g_Ah[NTE];   // tril(A) hi, [M,K] K-major
__device__ __align__(1024) __nv_bfloat16 g_Al[NTE];   // tril(A) lo
__device__ __align__(1024) __nv_bfloat16 g_Bth[NTE];  // tril(B)^T hi, [N,K] K-major
__device__ __align__(1024) __nv_bfloat16 g_Btl[NTE];  // tril(B)^T lo

// ---------------- helpers ---------------------------------------------------
static __device__ __forceinline__ uint32_t smem_u32(const void* p) {
    return (uint32_t)__cvta_generic_to_shared(p);
}

static __device__ __forceinline__ void cp_async16(uint32_t dst, const void* src) {
    asm volatile("cp.async.cg.shared.global [%0], [%1], 16;" :: "r"(dst), "l"(src));
}
static __device__ __forceinline__ void cp_commit() {
    asm volatile("cp.async.commit_group;" ::: "memory");
}
static __device__ __forceinline__ void cp_wait2() {
    asm volatile("cp.async.wait_group 2;" ::: "memory");
}

static __device__ __forceinline__ void ldsm4(uint32_t& r0, uint32_t& r1,
                                             uint32_t& r2, uint32_t& r3, uint32_t a) {
    asm volatile("ldmatrix.sync.aligned.m8n8.x4.shared.b16 {%0,%1,%2,%3}, [%4];"
                 : "=r"(r0), "=r"(r1), "=r"(r2), "=r"(r3) : "r"(a));
}

static __device__ __forceinline__ void mma16816(float* d, const uint32_t* a,
                                                const uint32_t* b) {
    asm volatile(
        "mma.sync.aligned.m16n8k16.row.col.f32.bf16.bf16.f32 "
        "{%0,%1,%2,%3}, {%4,%5,%6,%7}, {%8,%9}, {%0,%1,%2,%3};"
        : "+f"(d[0]), "+f"(d[1]), "+f"(d[2]), "+f"(d[3])
        : "r"(a[0]), "r"(a[1]), "r"(a[2]), "r"(a[3]), "r"(b[0]), "r"(b[1]));
}

// swizzled smem byte offset inside one 8KB tile: row r (0..127), 16B chunk c (0..3)
static __device__ __forceinline__ uint32_t swz(int r, int c) {
    return (uint32_t)(r * 64 + ((c ^ ((r >> 1) & 3)) << 4));
}

// ---------------- pre-pass: mask + bf16 hi/lo split of A (lower blocks only) -
__global__ void convert_split_A(const float* __restrict__ A) {
    size_t idx  = (size_t)blockIdx.x * blockDim.x + threadIdx.x;   // one float4
    size_t base = idx * 4;
    int i = (int)(base >> 12);     // row
    int k = (int)(base & 4095);    // col
    if ((k >> 7) > (i >> 7)) return;   // strictly-upper 128-blocks never read
    float4 v = *(const float4*)(A + base);
    float vv[4] = {v.x, v.y, v.z, v.w};
    __nv_bfloat16 h[4], l[4];
#pragma unroll
    for (int e = 0; e < 4; ++e) {
        float x = ((k + e) <= i) ? vv[e] : 0.0f;
        __nv_bfloat16 hi = __float2bfloat16(x);
        float res = x - __bfloat162float(hi);
        h[e] = hi;
        l[e] = __float2bfloat16(res);
    }
    __nv_bfloat162* ah = (__nv_bfloat162*)(g_Ah + base);
    __nv_bfloat162* al = (__nv_bfloat162*)(g_Al + base);
    ah[0] = __nv_bfloat162(h[0], h[1]); ah[1] = __nv_bfloat162(h[2], h[3]);
    al[0] = __nv_bfloat162(l[0], l[1]); al[1] = __nv_bfloat162(l[2], l[3]);
}

// ---------------- pre-pass: mask + transpose + split of B (64x64 tiles) -----
__global__ void transpose_split_B(const float* __restrict__ B) {
    __shared__ float tile[64][65];
    const int bk = blockIdx.y;   // 64-wide k-tile
    const int bn = blockIdx.x;   // 64-wide n-tile
    if ((bn >> 1) > (bk >> 1)) return;   // keep only k128-block >= n128-block
    const int tx = threadIdx.x;  // 0..63
    const int ty = threadIdx.y;  // 0..3
    const int k0 = bk * 64, n0 = bn * 64;
#pragma unroll
    for (int r = ty; r < 64; r += 4) {
        int k = k0 + r, n = n0 + tx;
        float v = B[(size_t)k * ND + n];
        tile[r][tx] = (n <= k) ? v : 0.0f;
    }
    __syncthreads();
#pragma unroll
    for (int r = ty; r < 64; r += 4) {
        int n = n0 + r, k = k0 + tx;
        float x = tile[tx][r];   // = masked B[k][n]
        __nv_bfloat16 hi = __float2bfloat16(x);
        float res = x - __bfloat162float(hi);
        g_Bth[(size_t)n * ND + k] = hi;
        g_Btl[(size_t)n * ND + k] = __float2bfloat16(res);
    }
}

// ---------------- main GEMM: mma.sync bf16 x3 + upper-tile zeroing ----------
#define STAGES 6
#define TILE_BYTES 8192                     // one 128x32 bf16 tile
#define STAGE_BYTES (4 * TILE_BYTES)        // Ah, Al, Bh, Bl
#define GEMM_SMEM (STAGES * STAGE_BYTES)    // 196608

__global__ __launch_bounds__(256, 1)
void trimm_gemm(float* __restrict__ C) {
    extern __shared__ char smem[];
    const uint32_t sb = smem_u32(smem);
    const int tid = threadIdx.x;

    // ---- blocks >= 528: zero one strictly-upper 128x128 tile and exit ------
    if (blockIdx.x >= 528) {
        int uid = blockIdx.x - 528;
        int r, cum = 0;
        for (r = 0; r < 32; ++r) {
            int cnt = 31 - r;
            if (uid < cum + cnt) break;
            cum += cnt;
        }
        const int zbi = r, zbj = r + 1 + (uid - cum);
        float4* dst = (float4*)(C + (size_t)zbi * 128 * ND + zbj * 128);
        const float4 z = make_float4(0.f, 0.f, 0.f, 0.f);
#pragma unroll
        for (int it = 0; it < 16; ++it) {
            int c = it * 256 + tid;          // 0..4095 float4 chunks
            int row = c >> 5, q = c & 31;
            dst[(size_t)row * (ND / 4) + q] = z;
        }
        return;
    }

    const int wid = tid >> 5;
    const int lid = tid & 31;
    const int wm = wid & 1;        // 0..1 (M)
    const int wn = wid >> 1;       // 0..3 (N)

    // tile map: heaviest diagonals first (d = bi-bj descending)
    int id = blockIdx.x;
    int dd, cum = 0;
    for (dd = 31; dd > 0; --dd) {
        int cnt = 32 - dd;
        if (id < cum + cnt) break;
        cum += cnt;
    }
    const int bj = id - cum;
    const int bi = bj + dd;

    const int kt0 = bj * 128;
    const int KT  = (bi - bj + 1) * 4;   // number of K=32 stages (even, >= 4)

    // per-thread cp.async chunk coords: two chunks per 8KB tile
    const int r0g = tid >> 2, c0g = tid & 3;               // chunk tid
    const int r1g = (tid + 256) >> 2, c1g = tid & 3;       // chunk tid+256

    const __nv_bfloat16* srcs[4] = {g_Ah, g_Al, g_Bth, g_Btl};
    const int rowbase[4] = {bi * 128, bi * 128, bj * 128, bj * 128};

    // issue one stage's loads into smem slot s
    auto issue = [&](int s, int kt) {
        uint32_t stage_base = sb + (uint32_t)s * STAGE_BYTES;
#pragma unroll
        for (int a = 0; a < 4; ++a) {
            const __nv_bfloat16* src = srcs[a];
            uint32_t tb = stage_base + a * TILE_BYTES;
            cp_async16(tb + swz(r0g, c0g),
                       src + (size_t)(rowbase[a] + r0g) * ND + kt + c0g * 8);
            cp_async16(tb + swz(r1g, c1g),
                       src + (size_t)(rowbase[a] + r1g) * ND + kt + c1g * 8);
        }
    };

    float acc[4][4][4];
#pragma unroll
    for (int a = 0; a < 4; ++a)
#pragma unroll
        for (int b = 0; b < 4; ++b)
#pragma unroll
            for (int c = 0; c < 4; ++c) acc[a][b][c] = 0.f;

    const int g  = lid >> 3;   // ldmatrix group 0..3
    const int rr = lid & 7;

    // compute one K=32 stage from smem slot
    auto compute_stage = [&](int slot) {
        const uint32_t stage = sb + (uint32_t)slot * STAGE_BYTES;
        const uint32_t aH = stage;
        const uint32_t bH = stage + 2 * TILE_BYTES;
#pragma unroll
        for (int ks = 0; ks < 2; ++ks) {
            const int c0 = ks * 2;
            uint32_t ah[4][4], al[4][4], bh[4][2], bl[4][2];
#pragma unroll
            for (int tm = 0; tm < 4; ++tm) {
                int r = wm * 64 + tm * 16 + (g & 1) * 8 + rr;
                uint32_t off = swz(r, c0 + (g >> 1));
                ldsm4(ah[tm][0], ah[tm][1], ah[tm][2], ah[tm][3], aH + off);
                ldsm4(al[tm][0], al[tm][1], al[tm][2], al[tm][3], aH + TILE_BYTES + off);
            }
#pragma unroll
            for (int p = 0; p < 2; ++p) {
                int r = wn * 32 + p * 16 + (g >> 1) * 8 + rr;
                uint32_t off = swz(r, c0 + (g & 1));
                uint32_t h0, h1, h2, h3;
                ldsm4(h0, h1, h2, h3, bH + off);
                bh[p * 2 + 0][0] = h0; bh[p * 2 + 0][1] = h1;
                bh[p * 2 + 1][0] = h2; bh[p * 2 + 1][1] = h3;
                ldsm4(h0, h1, h2, h3, bH + TILE_BYTES + off);
                bl[p * 2 + 0][0] = h0; bl[p * 2 + 0][1] = h1;
                bl[p * 2 + 1][0] = h2; bl[p * 2 + 1][1] = h3;
            }
#pragma unroll
            for (int tm = 0; tm < 4; ++tm)
#pragma unroll
                for (int tn = 0; tn < 4; ++tn) {
                    mma16816(acc[tm][tn], ah[tm], bh[tn]);
                    mma16816(acc[tm][tn], ah[tm], bl[tn]);
                    mma16816(acc[tm][tn], al[tm], bh[tn]);
                }
        }
    };

    // prologue: stages 0,1
    issue(0, kt0);      cp_commit();
    issue(1, kt0 + 32); cp_commit();

    // main loop: two stages per barrier.
    // invariant: commits after iter-j issue phase = j+4  ->  wait_group 2
    // completes stages <= j+1. Slot collision check (skew < 1 barrier):
    // writes {j+2, j+3} vs laggard reads {j-2, j-1} mod 6 -> diffs {3,4,5} != 0.
    for (int j = 0; j < KT; j += 2) {
        if (j + 2 < KT) issue((j + 2) % STAGES, kt0 + (j + 2) * 32);
        cp_commit();
        if (j + 3 < KT) issue((j + 3) % STAGES, kt0 + (j + 3) * 32);
        cp_commit();
        cp_wait2();
        __syncthreads();
        compute_stage(j % STAGES);
        compute_stage((j + 1) % STAGES);
    }

    // epilogue: write fp32 accumulators to C
#pragma unroll
    for (int tm = 0; tm < 4; ++tm) {
#pragma unroll
        for (int tn = 0; tn < 4; ++tn) {
            int row = bi * 128 + wm * 64 + tm * 16 + (lid >> 2);
            int col = bj * 128 + wn * 32 + tn * 8 + (lid & 3) * 2;
            float2 v0 = make_float2(acc[tm][tn][0], acc[tm][tn][1]);
            float2 v1 = make_float2(acc[tm][tn][2], acc[tm][tn][3]);
            *(float2*)(C + (size_t)row * ND + col)       = v0;
            *(float2*)(C + (size_t)(row + 8) * ND + col) = v1;
        }
    }
}

// ---------------- launch ----------------------------------------------------
extern "C" void kernel_launch(void* const* d_in, const int* in_sizes, int n_in,
                              void* d_out, int out_size) {
    const float* A = (const float*)d_in[0];
    const float* B = (const float*)d_in[1];
    float* C = (float*)d_out;

    cudaFuncSetAttribute(trimm_gemm, cudaFuncAttributeMaxDynamicSharedMemorySize, GEMM_SMEM);

    convert_split_A<<<16384, 256>>>(A);
    transpose_split_B<<<dim3(64, 64), dim3(64, 4)>>>(B);
    trimm_gemm<<<1024, 256, GEMM_SMEM>>>(C);
}